// round 16
// baseline (speedup 1.0000x reference)
#include <cuda_runtime.h>
#include <math.h>

// StatisticalFeatureExtractor: (B=64, C=16, T=65536) fp32 -> (B, C, 17) fp32
// One CTA (512 thr) per row, 2 CTAs/SM. Two passes (pass 2 L2-resident):
//   pass 1 (HBM): S1, S2, sum|x|, min, max, zero-crossings
//   pass 2 (L2):  sum sqrt|x| (MUFU), centered d2,d3,d4, mean-crossings
// Branch-free sign logic; shfl cross-chunk pairs; warp-span boundary pairs
// in one cleanup step; unroll 8 for MLP.

#define TLEN    65536
#define CHUNKS  (TLEN / 4)
#define THREADS 512
#define NWARP   (THREADS / 32)
#define EPSV    1e-8

typedef unsigned long long u64;

__device__ __forceinline__ u64 pk2(float x, float y) {
    u64 r; asm("mov.b64 %0, {%1, %2};" : "=l"(r) : "f"(x), "f"(y)); return r;
}
__device__ __forceinline__ void up2(u64 a, float& x, float& y) {
    asm("mov.b64 {%0, %1}, %2;" : "=f"(x), "=f"(y) : "l"(a));
}
__device__ __forceinline__ u64 add2(u64 a, u64 b) {
    u64 r; asm("add.rn.f32x2 %0, %1, %2;" : "=l"(r) : "l"(a), "l"(b)); return r;
}
__device__ __forceinline__ u64 mul2(u64 a, u64 b) {
    u64 r; asm("mul.rn.f32x2 %0, %1, %2;" : "=l"(r) : "l"(a), "l"(b)); return r;
}
__device__ __forceinline__ u64 fma2(u64 a, u64 b, u64 c) {
    u64 r; asm("fma.rn.f32x2 %0, %1, %2, %3;" : "=l"(r) : "l"(a), "l"(b), "l"(c)); return r;
}
__device__ __forceinline__ float sqrt_approx(float v) {
    float r; asm("sqrt.approx.f32 %0, %1;" : "=f"(r) : "f"(v)); return r;
}
__device__ __forceinline__ float hsum2(u64 a) { float x, y; up2(a, x, y); return x + y; }

__device__ __forceinline__ float warp_sum(float v) {
#pragma unroll
    for (int o = 16; o; o >>= 1) v += __shfl_xor_sync(0xffffffffu, v, o);
    return v;
}
__device__ __forceinline__ int warp_sumi(int v) {
#pragma unroll
    for (int o = 16; o; o >>= 1) v += __shfl_xor_sync(0xffffffffu, v, o);
    return v;
}
__device__ __forceinline__ float warp_max(float v) {
#pragma unroll
    for (int o = 16; o; o >>= 1) v = fmaxf(v, __shfl_xor_sync(0xffffffffu, v, o));
    return v;
}
__device__ __forceinline__ float warp_min(float v) {
#pragma unroll
    for (int o = 16; o; o >>= 1) v = fminf(v, __shfl_xor_sync(0xffffffffu, v, o));
    return v;
}

__global__ __launch_bounds__(THREADS, 2)
void stat_feat_kernel(const float* __restrict__ x, float* __restrict__ out) {
    const int row = blockIdx.x;
    const float* __restrict__ xr = x + (size_t)row * TLEN;
    const float4* __restrict__ x4 = reinterpret_cast<const float4*>(xr);

    const int tid  = threadIdx.x;
    const int wid  = tid >> 5;
    const int lane = tid & 31;
    const unsigned vmask = (lane != 31) ? 1u : 0u;

    __shared__ float w_a[NWARP], w_b[NWARP], w_c[NWARP], w_d[NWARP];
    __shared__ float w_mx[NWARP], w_mn[NWARP];
    __shared__ int   w_i[NWARP], w_j[NWARP];
    __shared__ float s_mean;
    __shared__ float s_res[6];     // S1, S2, Sa, max, min (Sq filled in stage 2)
    __shared__ int   s_zc;

    const u64 ABSM = 0x7fffffff7fffffffULL;

    // ================= pass 1: raw sums (HBM stream) =================
    u64 s1p = 0, s2p = 0, sap = 0;
    float mx = -INFINITY, mn = INFINITY;
    int zc = 0;

#pragma unroll 8
    for (int k = tid; k < CHUNKS; k += THREADS) {
        float4 v = x4[k];
        u64 plo = pk2(v.x, v.y), phi = pk2(v.z, v.w);

        s1p = add2(s1p, add2(plo, phi));
        s2p = fma2(plo, plo, s2p);
        s2p = fma2(phi, phi, s2p);

        u64 alo = plo & ABSM, ahi = phi & ABSM;
        sap = add2(sap, add2(alo, ahi));

        mx = fmaxf(mx, fmaxf(fmaxf(v.x, v.y), fmaxf(v.z, v.w)));
        mn = fminf(mn, fminf(fminf(v.x, v.y), fminf(v.z, v.w)));

        unsigned u0 = __float_as_uint(v.x), u1 = __float_as_uint(v.y);
        unsigned u2 = __float_as_uint(v.z), u3 = __float_as_uint(v.w);
        unsigned nu0 = __shfl_down_sync(0xffffffffu, u0, 1);
        zc += (int)(((u0 ^ u1) >> 31) + ((u1 ^ u2) >> 31) + ((u2 ^ u3) >> 31)
                    + (((u3 ^ nu0) >> 31) & vmask));
    }

    {
        float s1 = hsum2(s1p), s2 = hsum2(s2p), sa = hsum2(sap);
        s1 = warp_sum(s1); s2 = warp_sum(s2); sa = warp_sum(sa);
        mx = warp_max(mx); mn = warp_min(mn); zc = warp_sumi(zc);
        if (lane == 0) {
            w_a[wid] = s1; w_b[wid] = s2; w_c[wid] = sa;
            w_mx[wid] = mx; w_mn[wid] = mn; w_i[wid] = zc;
        }
    }
    __syncthreads();
    if (tid == 0) {
        double S1 = 0, S2 = 0, Sa = 0;
        float rmx = -INFINITY, rmn = INFINITY;
        int rzc = 0;
        for (int i = 0; i < NWARP; i++) {
            S1 += (double)w_a[i]; S2 += (double)w_b[i]; Sa += (double)w_c[i];
            rmx = fmaxf(rmx, w_mx[i]); rmn = fminf(rmn, w_mn[i]);
            rzc += w_i[i];
        }
        s_res[0] = (float)S1; s_res[1] = (float)S2; s_res[2] = (float)Sa;
        s_res[3] = rmx; s_res[4] = rmn;
        s_zc = rzc;
        s_mean = (float)(S1 * (1.0 / (double)TLEN));
    }
    __syncthreads();

    const float mean = s_mean;
    const u64 nm2 = pk2(-mean, -mean);

    // ================= pass 2: sqrt|x| + centered moments + mean crossings (L2) =================
    u64 d2p = 0, d3p = 0, d4p = 0;
    float sq0 = 0.f, sq1 = 0.f;
    int mc = 0;

#pragma unroll 8
    for (int k = tid; k < CHUNKS; k += THREADS) {
        float4 v = x4[k];
        u64 plo = pk2(v.x, v.y), phi = pk2(v.z, v.w);

        // sqrt-of-abs (MUFU) — moved here from pass 1
        u64 alo = plo & ABSM, ahi = phi & ABSM;
        float b0, b1, b2, b3;
        up2(alo, b0, b1); up2(ahi, b2, b3);
        sq0 += sqrt_approx(b0) + sqrt_approx(b1);
        sq1 += sqrt_approx(b2) + sqrt_approx(b3);

        // centered moments
        u64 dlo = add2(plo, nm2), dhi = add2(phi, nm2);
        u64 tlo = mul2(dlo, dlo), thi = mul2(dhi, dhi);
        d2p = add2(d2p, add2(tlo, thi));
        d3p = fma2(tlo, dlo, d3p);
        d3p = fma2(thi, dhi, d3p);
        d4p = fma2(tlo, tlo, d4p);
        d4p = fma2(thi, thi, d4p);

        // mean crossings
        float d0, d1, d2v, d3v;
        up2(dlo, d0, d1); up2(dhi, d2v, d3v);
        unsigned u0 = __float_as_uint(d0), u1 = __float_as_uint(d1);
        unsigned u2 = __float_as_uint(d2v), u3 = __float_as_uint(d3v);
        unsigned nu0 = __shfl_down_sync(0xffffffffu, u0, 1);
        mc += (int)(((u0 ^ u1) >> 31) + ((u1 ^ u2) >> 31) + ((u2 ^ u3) >> 31)
                    + (((u3 ^ nu0) >> 31) & vmask));
    }

    // ---------- cleanup: 511 warp-span boundary pairs (zcr & mcr), L2 hits ----------
    int zce = 0;
    if (tid < 511) {
        float a = __ldg(xr + 128 * tid + 127);
        float b = __ldg(xr + 128 * tid + 128);
        zce = (int)((__float_as_uint(a) ^ __float_as_uint(b)) >> 31);
        float ca = a - mean, cb = b - mean;
        mc += (int)((__float_as_uint(ca) ^ __float_as_uint(cb)) >> 31);
    }

    {
        float d2 = hsum2(d2p), d3 = hsum2(d3p), d4 = hsum2(d4p);
        float sqv = sq0 + sq1;
        d2 = warp_sum(d2); d3 = warp_sum(d3); d4 = warp_sum(d4); sqv = warp_sum(sqv);
        mc = warp_sumi(mc); zce = warp_sumi(zce);
        if (lane == 0) {
            w_a[wid] = d2; w_b[wid] = d3; w_c[wid] = d4; w_d[wid] = sqv;
            w_i[wid] = mc; w_j[wid] = zce;
        }
    }
    __syncthreads();

    if (tid == 0) {
        double D2 = 0.0, D3 = 0.0, D4 = 0.0, Sq = 0.0;
        int rmc = 0, rzce = 0;
        for (int i = 0; i < NWARP; i++) {
            D2 += (double)w_a[i]; D3 += (double)w_b[i]; D4 += (double)w_c[i];
            Sq += (double)w_d[i];
            rmc += w_i[i]; rzce += w_j[i];
        }

        const double Td   = (double)TLEN;
        const double invT = 1.0 / Td;
        double S1 = s_res[0], S2 = s_res[1], Sa = s_res[2];
        double pk = s_res[3], pkn = s_res[4];
        int    zct = s_zc + rzce;

        double meanv     = S1 * invT;
        double var       = D2 / (Td - 1.0);
        double stdv      = sqrt(var);
        double sq_mean   = S2 * invT;
        double rms       = sqrt(sq_mean);
        double ptp       = pk - pkn;
        double abs_peak  = fabs(pk);
        double crest     = abs_peak / (rms + EPSV);
        double mean_abs  = Sa * invT;
        double shape     = rms / (mean_abs + EPSV);
        double impulse   = abs_peak / (mean_abs + EPSV);
        double sqrt_mean = Sq * invT;
        double clearance = abs_peak / (sqrt_mean * sqrt_mean + EPSV);
        double skew      = (D3 * invT) / (stdv * stdv * stdv + EPSV);
        double kurt      = (D4 * invT) / (var * var + EPSV) - 3.0;
        double zcr       = (double)zct / (Td - 1.0);
        double mcr       = (double)rmc / (Td - 1.0);
        double margin    = abs_peak / (sqrt_mean + EPSV);
        double energy    = S2;

        float* o = out + (size_t)row * 17;
        o[0]  = (float)meanv;
        o[1]  = (float)stdv;
        o[2]  = (float)var;
        o[3]  = (float)rms;
        o[4]  = (float)pk;
        o[5]  = (float)pkn;
        o[6]  = (float)ptp;
        o[7]  = (float)crest;
        o[8]  = (float)shape;
        o[9]  = (float)impulse;
        o[10] = (float)clearance;
        o[11] = (float)skew;
        o[12] = (float)kurt;
        o[13] = (float)zcr;
        o[14] = (float)mcr;
        o[15] = (float)margin;
        o[16] = (float)energy;
    }
}

extern "C" void kernel_launch(void* const* d_in, const int* in_sizes, int n_in,
                              void* d_out, int out_size) {
    const float* x = (const float*)d_in[0];
    float* out = (float*)d_out;
    int rows = in_sizes[0] / TLEN;   // 64*16 = 1024
    stat_feat_kernel<<<rows, THREADS>>>(x, out);
}